// round 12
// baseline (speedup 1.0000x reference)
#include <cuda_runtime.h>
#include <cuda_fp16.h>
#include <math_constants.h>
#include <cstdint>

#define N_NODES 50000
#define N_EDGES 800000
#define M_TOT   850000   // edges + self loops
#define D 128

#define SCAN_CHUNK 1024
#define SCAN_NBLK  ((N_NODES + SCAN_CHUNK - 1) / SCAN_CHUNK)   // 49

typedef unsigned long long u64;

// ---------------- scratch (device globals; no allocation allowed) ----------
__device__ float  g_sum[1];
__device__ int    g_tick;
__device__ int    g_deg[N_NODES + 1];
__device__ int    g_rowptr[N_NODES + 1];
__device__ int    g_cnt[N_NODES];
__device__ int    g_blk[SCAN_NBLK];
__device__ int    g_off[SCAN_NBLK];
__device__ int2   g_csr[M_TOT];                 // {src | vocab<<17, weight-as-int}
__device__ float  g_tl[128 * D];                // emb@W1l + b1l  (per-vocab table)
__device__ float  g_tr[128 * D];                // emb@W1r + b1r
__device__ __align__(8) __half g_xlh[N_NODES * D];  // xl (layer2 left proj), fp16
__device__ float4 g_xr[N_NODES * 32];
__device__ float4 g_x1[N_NODES * 32];

// ---------------- f32x2 helpers (FFMA2: PTX-only on sm_103a) ---------------
__device__ __forceinline__ u64 pk2(float a, float b) {
    u64 r; asm("mov.b64 %0,{%1,%2};" : "=l"(r) : "f"(a), "f"(b)); return r;
}
__device__ __forceinline__ void upk2(u64 v, float& a, float& b) {
    asm("mov.b64 {%0,%1},%2;" : "=f"(a), "=f"(b) : "l"(v));
}
__device__ __forceinline__ u64 ffma2(u64 a, u64 b, u64 c) {
    u64 d; asm("fma.rn.f32x2 %0,%1,%2,%3;" : "=l"(d) : "l"(a), "l"(b), "l"(c)); return d;
}

// ---------------- setup: deg init + counter resets -------------------------
__global__ void setup_kernel() {
    int i = blockIdx.x * blockDim.x + threadIdx.x;
    if (i <= N_NODES) g_deg[i] = (i < N_NODES) ? 1 : 0;   // +1 = self loop
    if (i == 0) { g_sum[0] = 0.f; g_tick = 0; }
}

// fused: histogram of dst + sum of edge weights
__global__ void hist_sumw_kernel(const int* __restrict__ ei, const float* __restrict__ ew) {
    int i = blockIdx.x * blockDim.x + threadIdx.x;
    float v = 0.f;
    if (i < N_EDGES) {
        atomicAdd(&g_deg[ei[N_EDGES + i]], 1);
        v = ew[i];
    }
    #pragma unroll
    for (int o = 16; o; o >>= 1) v += __shfl_xor_sync(0xffffffffu, v, o);
    if ((threadIdx.x & 31) == 0) atomicAdd(g_sum, v);
}

// ---------------- layer-1 vocab tables: T = emb @ W + b --------------------
__global__ void table_kernel(const float* __restrict__ emb,
                             const float* __restrict__ Wl, const float* __restrict__ bl,
                             const float* __restrict__ Wr, const float* __restrict__ br)
{
    const float* W = blockIdx.y ? Wr : Wl;
    const float* B = blockIdx.y ? br : bl;
    float*       T = blockIdx.y ? g_tr : g_tl;
    __shared__ float es[8][D];
    int v0 = blockIdx.x * 8;
    int tid = threadIdx.x;
    ((float4*)&es[0][0])[tid] = ((const float4*)(emb + v0 * D))[tid];   // 256 f4 = 8 rows
    __syncthreads();
    int n = tid & 127, h = tid >> 7;
    float bn = B[n];
    #pragma unroll
    for (int j = 0; j < 4; j++) {
        int vr = h * 4 + j;
        float s = bn;
        #pragma unroll 8
        for (int k = 0; k < D; k++) s += es[vr][k] * W[k * D + n];
        T[(v0 + vr) * D + n] = s;
    }
}

// ---- scan phase 1+2 fused: per-chunk sums, last block scans them ----------
__global__ void scan_pb_kernel() {
    __shared__ int ws[8];
    __shared__ int s_last;
    int b = blockIdx.x, tid = threadIdx.x;
    int base = b * SCAN_CHUNK + tid * 4;
    int s = 0;
    #pragma unroll
    for (int j = 0; j < 4; j++) {
        int idx = base + j;
        if (idx < N_NODES) s += g_deg[idx];
    }
    #pragma unroll
    for (int o = 16; o; o >>= 1) s += __shfl_xor_sync(0xffffffffu, s, o);
    if ((tid & 31) == 0) ws[tid >> 5] = s;
    __syncthreads();
    if (tid < 8) {
        int v = ws[tid];
        #pragma unroll
        for (int o = 4; o; o >>= 1) v += __shfl_xor_sync(0xffu, v, o);
        if (tid == 0) {
            g_blk[b] = v;
            __threadfence();
            int t = atomicAdd(&g_tick, 1);
            s_last = (t == SCAN_NBLK - 1);
        }
    }
    __syncthreads();
    if (!s_last || tid >= 32) return;
    int lane = tid;
    int v0 = (lane < SCAN_NBLK) ? g_blk[lane] : 0;
    int v1 = (lane + 32 < SCAN_NBLK) ? g_blk[lane + 32] : 0;
    int x = v0;
    #pragma unroll
    for (int o = 1; o < 32; o <<= 1) {
        int y = __shfl_up_sync(0xffffffffu, x, o);
        if (lane >= o) x += y;
    }
    int tot0 = __shfl_sync(0xffffffffu, x, 31);
    int z = v1;
    #pragma unroll
    for (int o = 1; o < 32; o <<= 1) {
        int y = __shfl_up_sync(0xffffffffu, z, o);
        if (lane >= o) z += y;
    }
    if (lane < SCAN_NBLK)      g_off[lane]      = x - v0;
    if (lane + 32 < SCAN_NBLK) g_off[lane + 32] = tot0 + z - v1;
}

// ---- scan phase 3: per-chunk exclusive scan + add block offset ------------
__global__ void scan_final_kernel() {
    __shared__ int ws[8];
    int b = blockIdx.x, tid = threadIdx.x;
    int lane = tid & 31, wid = tid >> 5;
    int base = b * SCAN_CHUNK + tid * 4;
    int d0 = 0, d1 = 0, d2 = 0, d3 = 0;
    if (base + 0 < N_NODES) d0 = g_deg[base + 0];
    if (base + 1 < N_NODES) d1 = g_deg[base + 1];
    if (base + 2 < N_NODES) d2 = g_deg[base + 2];
    if (base + 3 < N_NODES) d3 = g_deg[base + 3];
    int tsum = d0 + d1 + d2 + d3;
    int x = tsum;
    #pragma unroll
    for (int o = 1; o < 32; o <<= 1) {
        int y = __shfl_up_sync(0xffffffffu, x, o);
        if (lane >= o) x += y;
    }
    if (lane == 31) ws[wid] = x;
    __syncthreads();
    if (tid < 8) {
        int w = ws[tid];
        #pragma unroll
        for (int o = 1; o < 8; o <<= 1) {
            int y = __shfl_up_sync(0xffu, w, o);
            if (tid >= o) w += y;
        }
        ws[tid] = w;
    }
    __syncthreads();
    int woff = (wid > 0) ? ws[wid - 1] : 0;
    int excl = g_off[b] + woff + (x - tsum);
    int e0 = excl, e1 = e0 + d0, e2 = e1 + d1, e3 = e2 + d2;
    if (base + 0 < N_NODES) { g_rowptr[base + 0] = e0; g_cnt[base + 0] = e0; }
    if (base + 1 < N_NODES) { g_rowptr[base + 1] = e1; g_cnt[base + 1] = e1; }
    if (base + 2 < N_NODES) { g_rowptr[base + 2] = e2; g_cnt[base + 2] = e2; }
    if (base + 3 < N_NODES) { g_rowptr[base + 3] = e3; g_cnt[base + 3] = e3; }
    if (b == 0 && tid == 0) g_rowptr[N_NODES] = M_TOT;
}

// packs src index (17 bits) + src vocab id (7 bits) into csr.x
__global__ void scatter_kernel(const int* __restrict__ ei, const float* __restrict__ ew,
                               const int* __restrict__ node_ids) {
    int i = blockIdx.x * blockDim.x + threadIdx.x;
    if (i >= M_TOT) return;
    int s, d; float w;
    if (i < N_EDGES) { s = ei[i]; d = ei[N_EDGES + i]; w = ew[i]; }
    else             { s = d = i - N_EDGES; w = g_sum[0] * (1.0f / N_EDGES); }
    int packed = s | (node_ids[s] << 17);
    int pos = atomicAdd(&g_cnt[d], 1);
    g_csr[pos] = make_int2(packed, __float_as_int(w));
}

// ---------------- GEMM (layer 2): Y = X @ W + B, FFMA2 --------------------
// blockIdx.y == 0 -> xl projection, written as fp16 (only attn2 reads it)
// blockIdx.y == 1 -> xr projection, written as fp32
__global__ __launch_bounds__(256, 4) void gemm2_kernel(
    const float* __restrict__ X,
    const float* __restrict__ Wl, const float* __restrict__ Bl,
    const float* __restrict__ Wr, const float* __restrict__ Br,
    float* __restrict__ Yr)
{
    const float* W = (blockIdx.y == 0) ? Wl : Wr;
    const float* B = (blockIdx.y == 0) ? Bl : Br;

    __shared__ float2 xs[32 * 128];           // [row_pair][k]
    const int tx = threadIdx.x, ty = threadIdx.y;
    const int t  = ty * 32 + tx;
    const int r0 = blockIdx.x * 64;

    #pragma unroll
    for (int i = 0; i < 4; i++) {
        int u  = t + 256 * i;                 // 0..1023
        int rp = u >> 5, c4 = u & 31;
        int ra = r0 + 2 * rp, rb = ra + 1;
        float4 a = (ra < N_NODES) ? *(const float4*)(X + ra * D + c4 * 4) : make_float4(0,0,0,0);
        float4 b = (rb < N_NODES) ? *(const float4*)(X + rb * D + c4 * 4) : make_float4(0,0,0,0);
        xs[rp * 128 + 4 * c4 + 0] = make_float2(a.x, b.x);
        xs[rp * 128 + 4 * c4 + 1] = make_float2(a.y, b.y);
        xs[rp * 128 + 4 * c4 + 2] = make_float2(a.z, b.z);
        xs[rp * 128 + 4 * c4 + 3] = make_float2(a.w, b.w);
    }
    __syncthreads();

    u64 acc[4][4];
    #pragma unroll
    for (int j = 0; j < 4; j++)
        #pragma unroll
        for (int c = 0; c < 4; c++) acc[j][c] = 0ull;

    const float4* W4 = (const float4*)W;
    #pragma unroll 4
    for (int k = 0; k < D; k += 2) {
        float4 wA = W4[k * 32 + tx];
        float4 wB = W4[(k + 1) * 32 + tx];
        u64 wA0 = pk2(wA.x, wA.x), wA1 = pk2(wA.y, wA.y);
        u64 wA2 = pk2(wA.z, wA.z), wA3 = pk2(wA.w, wA.w);
        u64 wB0 = pk2(wB.x, wB.x), wB1 = pk2(wB.y, wB.y);
        u64 wB2 = pk2(wB.z, wB.z), wB3 = pk2(wB.w, wB.w);
        #pragma unroll
        for (int j = 0; j < 4; j++) {
            float4 xv = *(const float4*)&xs[(ty * 4 + j) * 128 + k];
            u64 x0 = pk2(xv.x, xv.y);   // (row_e, row_o) at k
            u64 x1 = pk2(xv.z, xv.w);   // (row_e, row_o) at k+1
            acc[j][0] = ffma2(x0, wA0, acc[j][0]);
            acc[j][1] = ffma2(x0, wA1, acc[j][1]);
            acc[j][2] = ffma2(x0, wA2, acc[j][2]);
            acc[j][3] = ffma2(x0, wA3, acc[j][3]);
            acc[j][0] = ffma2(x1, wB0, acc[j][0]);
            acc[j][1] = ffma2(x1, wB1, acc[j][1]);
            acc[j][2] = ffma2(x1, wB2, acc[j][2]);
            acc[j][3] = ffma2(x1, wB3, acc[j][3]);
        }
    }

    float4 b4 = *(const float4*)(B + tx * 4);
    #pragma unroll
    for (int j = 0; j < 4; j++) {
        int rp = ty * 4 + j;
        int ra = r0 + 2 * rp, rb = ra + 1;
        float e0,o0,e1,o1,e2,o2,e3,o3;
        upk2(acc[j][0], e0, o0); upk2(acc[j][1], e1, o1);
        upk2(acc[j][2], e2, o2); upk2(acc[j][3], e3, o3);
        e0 += b4.x; e1 += b4.y; e2 += b4.z; e3 += b4.w;
        o0 += b4.x; o1 += b4.y; o2 += b4.z; o3 += b4.w;
        if (blockIdx.y == 0) {
            if (ra < N_NODES) {
                __half2 h01 = __floats2half2_rn(e0, e1);
                __half2 h23 = __floats2half2_rn(e2, e3);
                uint2 pk; pk.x = *(uint32_t*)&h01; pk.y = *(uint32_t*)&h23;
                *(uint2*)(g_xlh + ra * D + tx * 4) = pk;
            }
            if (rb < N_NODES) {
                __half2 h01 = __floats2half2_rn(o0, o1);
                __half2 h23 = __floats2half2_rn(o2, o3);
                uint2 pk; pk.x = *(uint32_t*)&h01; pk.y = *(uint32_t*)&h23;
                *(uint2*)(g_xlh + rb * D + tx * 4) = pk;
            }
        } else {
            if (ra < N_NODES)
                *(float4*)(Yr + ra * D + tx * 4) = make_float4(e0, e1, e2, e3);
            if (rb < N_NODES)
                *(float4*)(Yr + rb * D + tx * 4) = make_float4(o0, o1, o2, o3);
        }
    }
}

// ---------------- attention pieces -----------------------------------------
__device__ __forceinline__ float warp_sum(float l) {
    l += __shfl_xor_sync(0xffffffffu, l, 16);
    l += __shfl_xor_sync(0xffffffffu, l, 8);
    l += __shfl_xor_sync(0xffffffffu, l, 4);
    l += __shfl_xor_sync(0xffffffffu, l, 2);
    l += __shfl_xor_sync(0xffffffffu, l, 1);
    return l;
}

// ---------------- layer-1 attention: xl/xr via 64KB vocab tables -----------
// No-max softmax (logits O(0.1); exp cannot overflow). Table is L1-hot, so
// 1-deep prefetch suffices here.
__global__ __launch_bounds__(256) void attn1_kernel(
    const int* __restrict__ node_ids, const float* __restrict__ emb,
    const float* __restrict__ We, const float* __restrict__ att,
    const float* __restrict__ bias, const float* __restrict__ gam,
    const float* __restrict__ bet, float* __restrict__ out)
{
    int gw   = (blockIdx.x * blockDim.x + threadIdx.x) >> 5;
    int lane = threadIdx.x & 31;
    if (gw >= N_NODES) return;
    int c = lane * 4;

    int vd = __ldg(node_ids + gw);
    float4 xr4 = *(const float4*)(g_tr + vd * D + c);
    float4 r4  = *(const float4*)(emb + vd * D + c);
    float4 We4 = *(const float4*)(We + c);
    float4 at4 = *(const float4*)(att + c);

    int beg = g_rowptr[gw], end = g_rowptr[gw + 1];
    float s = 0.f;
    float ax = 0.f, ay = 0.f, az = 0.f, aw = 0.f;

    int2  e0 = g_csr[beg];
    float wc = __int_as_float(e0.y);
    float4 xv = *(const float4*)(g_tl + (e0.x >> 17) * D + c);

    for (int i = beg; i < end; i++) {
        int   ni  = (i + 1 < end) ? i + 1 : i;
        int2  ne  = g_csr[ni];
        float nw  = __int_as_float(ne.y);
        float4 nxv = *(const float4*)(g_tl + (ne.x >> 17) * D + c);

        float t0 = xv.x + xr4.x + wc * We4.x; t0 = fmaxf(t0, 0.2f * t0);
        float t1 = xv.y + xr4.y + wc * We4.y; t1 = fmaxf(t1, 0.2f * t1);
        float t2 = xv.z + xr4.z + wc * We4.z; t2 = fmaxf(t2, 0.2f * t2);
        float t3 = xv.w + xr4.w + wc * We4.w; t3 = fmaxf(t3, 0.2f * t3);
        float l = warp_sum(t0 * at4.x + t1 * at4.y + t2 * at4.z + t3 * at4.w);
        float e = __expf(l);
        s  += e;
        ax += e * xv.x;
        ay += e * xv.y;
        az += e * xv.z;
        aw += e * xv.w;
        xv = nxv; wc = nw;
    }

    float inv = 1.0f / s;
    float4 b4 = *(const float4*)(bias + c);
    float hx = r4.x + ax * inv + b4.x;
    float hy = r4.y + ay * inv + b4.y;
    float hz = r4.z + az * inv + b4.z;
    float hw = r4.w + aw * inv + b4.w;

    float mu = warp_sum(hx + hy + hz + hw) * (1.0f / D);
    float dx = hx - mu, dy = hy - mu, dz = hz - mu, dw = hw - mu;
    float var = warp_sum(dx * dx + dy * dy + dz * dz + dw * dw) * (1.0f / D);
    float sc  = rsqrtf(var + 1e-5f);

    float4 g4  = *(const float4*)(gam + c);
    float4 be4 = *(const float4*)(bet + c);
    float4 o;
    o.x = dx * sc * g4.x + be4.x;
    o.y = dy * sc * g4.y + be4.y;
    o.z = dz * sc * g4.z + be4.z;
    o.w = dw * sc * g4.w + be4.w;
    *(float4*)(out + gw * D + c) = o;
}

// ---------------- layer-2 attention: fp16 xl gather, no-max softmax --------
// DEPTH-2 software pipeline: the xl gather hits L2 (~250 cyc) while the
// per-edge compute chain is only ~200 cyc, so 1-deep prefetch left exposed
// stalls. Edge i+2's CSR entry and row are issued while edge i computes.
__global__ __launch_bounds__(256) void attn2_kernel(
    const float* __restrict__ xr,
    const float* __restrict__ We, const float* __restrict__ att,
    const float* __restrict__ bias, const float* __restrict__ gam,
    const float* __restrict__ bet, const float* __restrict__ resid,
    float* __restrict__ out)
{
    int gw   = (blockIdx.x * blockDim.x + threadIdx.x) >> 5;
    int lane = threadIdx.x & 31;
    if (gw >= N_NODES) return;
    int c = lane * 4;

    float4 xr4 = *(const float4*)(xr + gw * D + c);
    float4 We4 = *(const float4*)(We + c);
    float4 at4 = *(const float4*)(att + c);

    int beg = g_rowptr[gw], end = g_rowptr[gw + 1], last = end - 1;
    float s = 0.f;
    float ax = 0.f, ay = 0.f, az = 0.f, aw = 0.f;

    // pipeline stages 0 (current) and 1 (next)
    int2  eA = g_csr[beg];
    int   i1 = (beg + 1 <= last) ? beg + 1 : last;
    int2  eB = g_csr[i1];
    float wA = __int_as_float(eA.y);
    float wB = __int_as_float(eB.y);
    uint2 xA = *(const uint2*)(g_xlh + (eA.x & 0x1FFFF) * D + c);
    uint2 xB = *(const uint2*)(g_xlh + (eB.x & 0x1FFFF) * D + c);

    for (int i = beg; i < end; i++) {
        // issue stage-2 loads (edge i+2) before touching stage-0 data
        int   i2 = (i + 2 <= last) ? i + 2 : last;
        int2  eC = g_csr[i2];
        float wC = __int_as_float(eC.y);
        uint2 xC = *(const uint2*)(g_xlh + (eC.x & 0x1FFFF) * D + c);

        float2 lo = __half22float2(*(__half2*)&xA.x);
        float2 hi = __half22float2(*(__half2*)&xA.y);
        float4 xv = make_float4(lo.x, lo.y, hi.x, hi.y);

        float t0 = xv.x + xr4.x + wA * We4.x; t0 = fmaxf(t0, 0.2f * t0);
        float t1 = xv.y + xr4.y + wA * We4.y; t1 = fmaxf(t1, 0.2f * t1);
        float t2 = xv.z + xr4.z + wA * We4.z; t2 = fmaxf(t2, 0.2f * t2);
        float t3 = xv.w + xr4.w + wA * We4.w; t3 = fmaxf(t3, 0.2f * t3);
        float l = warp_sum(t0 * at4.x + t1 * at4.y + t2 * at4.z + t3 * at4.w);
        float e = __expf(l);
        s  += e;
        ax += e * xv.x;
        ay += e * xv.y;
        az += e * xv.z;
        aw += e * xv.w;

        // rotate pipeline
        xA = xB; wA = wB;
        xB = xC; wB = wC;
    }

    float inv = 1.0f / s;
    float4 b4 = *(const float4*)(bias + c);
    float4 r4 = *(const float4*)(resid + gw * D + c);
    float hx = r4.x + ax * inv + b4.x;
    float hy = r4.y + ay * inv + b4.y;
    float hz = r4.z + az * inv + b4.z;
    float hw = r4.w + aw * inv + b4.w;

    float mu = warp_sum(hx + hy + hz + hw) * (1.0f / D);
    float dx = hx - mu, dy = hy - mu, dz = hz - mu, dw = hw - mu;
    float var = warp_sum(dx * dx + dy * dy + dz * dz + dw * dw) * (1.0f / D);
    float sc  = rsqrtf(var + 1e-5f);

    float4 g4  = *(const float4*)(gam + c);
    float4 be4 = *(const float4*)(bet + c);
    float4 o;
    o.x = dx * sc * g4.x + be4.x;
    o.y = dy * sc * g4.y + be4.y;
    o.z = dz * sc * g4.z + be4.z;
    o.w = dw * sc * g4.w + be4.w;
    *(float4*)(out + gw * D + c) = o;
}

// ---------------- host -----------------------------------------------------
extern "C" void kernel_launch(void* const* d_in, const int* in_sizes, int n_in,
                              void* d_out, int out_size)
{
    const int*   node_ids = (const int*)d_in[0];
    const int*   ei       = (const int*)d_in[1];
    const float* ew       = (const float*)d_in[2];
    const float* emb      = (const float*)d_in[3];
    const float* w1l = (const float*)d_in[4];
    const float* b1l = (const float*)d_in[5];
    const float* w1r = (const float*)d_in[6];
    const float* b1r = (const float*)d_in[7];
    const float* w1e = (const float*)d_in[8];
    const float* at1 = (const float*)d_in[9];
    const float* bi1 = (const float*)d_in[10];
    const float* g1  = (const float*)d_in[11];
    const float* be1 = (const float*)d_in[12];
    const float* w2l = (const float*)d_in[13];
    const float* b2l = (const float*)d_in[14];
    const float* w2r = (const float*)d_in[15];
    const float* b2r = (const float*)d_in[16];
    const float* w2e = (const float*)d_in[17];
    const float* at2 = (const float*)d_in[18];
    const float* bi2 = (const float*)d_in[19];
    const float* g2  = (const float*)d_in[20];
    const float* be2 = (const float*)d_in[21];
    float* out = (float*)d_out;

    float *xr, *x1;
    cudaGetSymbolAddress((void**)&xr, g_xr);
    cudaGetSymbolAddress((void**)&x1, g_x1);

    dim3 gb(32, 8);
    dim3 gemm_grid((N_NODES + 63) / 64, 2);      // 782 x 2
    dim3 tbl_grid(16, 2);
    const int AB = (N_NODES + 7) / 8;            // 6250 (8 warps/block)

    setup_kernel<<<(N_NODES + 256) / 256, 256>>>();                           // 1
    hist_sumw_kernel<<<(N_EDGES + 255) / 256, 256>>>(ei, ew);                 // 2
    table_kernel<<<tbl_grid, 256>>>(emb, w1l, b1l, w1r, b1r);                 // 3
    scan_pb_kernel<<<SCAN_NBLK, 256>>>();                                     // 4 <- profiled
    scan_final_kernel<<<SCAN_NBLK, 256>>>();                                  // 5
    scatter_kernel<<<(M_TOT + 255) / 256, 256>>>(ei, ew, node_ids);           // 6
    attn1_kernel<<<AB, 256>>>(node_ids, emb, w1e, at1, bi1, g1, be1, x1);     // 7
    gemm2_kernel<<<gemm_grid, gb>>>(x1, w2l, b2l, w2r, b2r, xr);              // 8
    attn2_kernel<<<AB, 256>>>(xr, w2e, at2, bi2, g2, be2, x1, out);           // 9
}

// round 13
// speedup vs baseline: 1.0515x; 1.0515x over previous
#include <cuda_runtime.h>
#include <cuda_fp16.h>
#include <math_constants.h>
#include <cstdint>

#define N_NODES 50000
#define N_EDGES 800000
#define M_TOT   850000   // edges + self loops
#define D 128

#define SCAN_CHUNK 1024
#define SCAN_NBLK  ((N_NODES + SCAN_CHUNK - 1) / SCAN_CHUNK)   // 49

typedef unsigned long long u64;

// ---------------- scratch (device globals; no allocation allowed) ----------
__device__ float  g_sum[1];
__device__ int    g_tick;
__device__ int    g_deg[N_NODES + 1];
__device__ int    g_rowptr[N_NODES + 1];
__device__ int    g_cnt[N_NODES];
__device__ int    g_blk[SCAN_NBLK];
__device__ int    g_off[SCAN_NBLK];
__device__ int2   g_csr[M_TOT];                 // {src | vocab<<17, weight-as-int}
__device__ __align__(8) __half g_tlh[128 * D];  // fp16 emb@W1l + b1l  (vocab table)
__device__ __align__(8) __half g_trh[128 * D];  // fp16 emb@W1r + b1r
__device__ __align__(8) __half g_xlh[N_NODES * D];  // xl (layer2 left proj), fp16
__device__ float4 g_xr[N_NODES * 32];
__device__ float4 g_x1[N_NODES * 32];

// ---------------- f32x2 helpers (FFMA2: PTX-only on sm_103a) ---------------
__device__ __forceinline__ u64 pk2(float a, float b) {
    u64 r; asm("mov.b64 %0,{%1,%2};" : "=l"(r) : "f"(a), "f"(b)); return r;
}
__device__ __forceinline__ void upk2(u64 v, float& a, float& b) {
    asm("mov.b64 {%0,%1},%2;" : "=f"(a), "=f"(b) : "l"(v));
}
__device__ __forceinline__ u64 ffma2(u64 a, u64 b, u64 c) {
    u64 d; asm("fma.rn.f32x2 %0,%1,%2,%3;" : "=l"(d) : "l"(a), "l"(b), "l"(c)); return d;
}

// ---------------- setup: deg init + counter resets -------------------------
__global__ void setup_kernel() {
    int i = blockIdx.x * blockDim.x + threadIdx.x;
    if (i <= N_NODES) g_deg[i] = (i < N_NODES) ? 1 : 0;   // +1 = self loop
    if (i == 0) { g_sum[0] = 0.f; g_tick = 0; }
}

// fused: histogram of dst + sum of edge weights
__global__ void hist_sumw_kernel(const int* __restrict__ ei, const float* __restrict__ ew) {
    int i = blockIdx.x * blockDim.x + threadIdx.x;
    float v = 0.f;
    if (i < N_EDGES) {
        atomicAdd(&g_deg[ei[N_EDGES + i]], 1);
        v = ew[i];
    }
    #pragma unroll
    for (int o = 16; o; o >>= 1) v += __shfl_xor_sync(0xffffffffu, v, o);
    if ((threadIdx.x & 31) == 0) atomicAdd(g_sum, v);
}

// ---------------- layer-1 vocab tables: T = fp16(emb @ W + b) --------------
__global__ void table_kernel(const float* __restrict__ emb,
                             const float* __restrict__ Wl, const float* __restrict__ bl,
                             const float* __restrict__ Wr, const float* __restrict__ br)
{
    const float* W = blockIdx.y ? Wr : Wl;
    const float* B = blockIdx.y ? br : bl;
    __half*      T = blockIdx.y ? g_trh : g_tlh;
    __shared__ float es[8][D];
    int v0 = blockIdx.x * 8;
    int tid = threadIdx.x;
    ((float4*)&es[0][0])[tid] = ((const float4*)(emb + v0 * D))[tid];   // 256 f4 = 8 rows
    __syncthreads();
    int n = tid & 127, h = tid >> 7;
    float bn = B[n];
    #pragma unroll
    for (int j = 0; j < 4; j++) {
        int vr = h * 4 + j;
        float s = bn;
        #pragma unroll 8
        for (int k = 0; k < D; k++) s += es[vr][k] * W[k * D + n];
        T[(v0 + vr) * D + n] = __float2half(s);
    }
}

// ---- scan phase 1+2 fused: per-chunk sums, last block scans them ----------
__global__ void scan_pb_kernel() {
    __shared__ int ws[8];
    __shared__ int s_last;
    int b = blockIdx.x, tid = threadIdx.x;
    int base = b * SCAN_CHUNK + tid * 4;
    int s = 0;
    #pragma unroll
    for (int j = 0; j < 4; j++) {
        int idx = base + j;
        if (idx < N_NODES) s += g_deg[idx];
    }
    #pragma unroll
    for (int o = 16; o; o >>= 1) s += __shfl_xor_sync(0xffffffffu, s, o);
    if ((tid & 31) == 0) ws[tid >> 5] = s;
    __syncthreads();
    if (tid < 8) {
        int v = ws[tid];
        #pragma unroll
        for (int o = 4; o; o >>= 1) v += __shfl_xor_sync(0xffu, v, o);
        if (tid == 0) {
            g_blk[b] = v;
            __threadfence();
            int t = atomicAdd(&g_tick, 1);
            s_last = (t == SCAN_NBLK - 1);
        }
    }
    __syncthreads();
    if (!s_last || tid >= 32) return;
    int lane = tid;
    int v0 = (lane < SCAN_NBLK) ? g_blk[lane] : 0;
    int v1 = (lane + 32 < SCAN_NBLK) ? g_blk[lane + 32] : 0;
    int x = v0;
    #pragma unroll
    for (int o = 1; o < 32; o <<= 1) {
        int y = __shfl_up_sync(0xffffffffu, x, o);
        if (lane >= o) x += y;
    }
    int tot0 = __shfl_sync(0xffffffffu, x, 31);
    int z = v1;
    #pragma unroll
    for (int o = 1; o < 32; o <<= 1) {
        int y = __shfl_up_sync(0xffffffffu, z, o);
        if (lane >= o) z += y;
    }
    if (lane < SCAN_NBLK)      g_off[lane]      = x - v0;
    if (lane + 32 < SCAN_NBLK) g_off[lane + 32] = tot0 + z - v1;
}

// ---- scan phase 3: per-chunk exclusive scan + add block offset ------------
__global__ void scan_final_kernel() {
    __shared__ int ws[8];
    int b = blockIdx.x, tid = threadIdx.x;
    int lane = tid & 31, wid = tid >> 5;
    int base = b * SCAN_CHUNK + tid * 4;
    int d0 = 0, d1 = 0, d2 = 0, d3 = 0;
    if (base + 0 < N_NODES) d0 = g_deg[base + 0];
    if (base + 1 < N_NODES) d1 = g_deg[base + 1];
    if (base + 2 < N_NODES) d2 = g_deg[base + 2];
    if (base + 3 < N_NODES) d3 = g_deg[base + 3];
    int tsum = d0 + d1 + d2 + d3;
    int x = tsum;
    #pragma unroll
    for (int o = 1; o < 32; o <<= 1) {
        int y = __shfl_up_sync(0xffffffffu, x, o);
        if (lane >= o) x += y;
    }
    if (lane == 31) ws[wid] = x;
    __syncthreads();
    if (tid < 8) {
        int w = ws[tid];
        #pragma unroll
        for (int o = 1; o < 8; o <<= 1) {
            int y = __shfl_up_sync(0xffu, w, o);
            if (tid >= o) w += y;
        }
        ws[tid] = w;
    }
    __syncthreads();
    int woff = (wid > 0) ? ws[wid - 1] : 0;
    int excl = g_off[b] + woff + (x - tsum);
    int e0 = excl, e1 = e0 + d0, e2 = e1 + d1, e3 = e2 + d2;
    if (base + 0 < N_NODES) { g_rowptr[base + 0] = e0; g_cnt[base + 0] = e0; }
    if (base + 1 < N_NODES) { g_rowptr[base + 1] = e1; g_cnt[base + 1] = e1; }
    if (base + 2 < N_NODES) { g_rowptr[base + 2] = e2; g_cnt[base + 2] = e2; }
    if (base + 3 < N_NODES) { g_rowptr[base + 3] = e3; g_cnt[base + 3] = e3; }
    if (b == 0 && tid == 0) g_rowptr[N_NODES] = M_TOT;
}

// packs src index (17 bits) + src vocab id (7 bits) into csr.x
__global__ void scatter_kernel(const int* __restrict__ ei, const float* __restrict__ ew,
                               const int* __restrict__ node_ids) {
    int i = blockIdx.x * blockDim.x + threadIdx.x;
    if (i >= M_TOT) return;
    int s, d; float w;
    if (i < N_EDGES) { s = ei[i]; d = ei[N_EDGES + i]; w = ew[i]; }
    else             { s = d = i - N_EDGES; w = g_sum[0] * (1.0f / N_EDGES); }
    int packed = s | (node_ids[s] << 17);
    int pos = atomicAdd(&g_cnt[d], 1);
    g_csr[pos] = make_int2(packed, __float_as_int(w));
}

// ---------------- GEMM (layer 2): Y = X @ W + B, FFMA2 --------------------
// blockIdx.y == 0 -> xl projection, written as fp16 (only attn2 reads it)
// blockIdx.y == 1 -> xr projection, written as fp32
__global__ __launch_bounds__(256, 4) void gemm2_kernel(
    const float* __restrict__ X,
    const float* __restrict__ Wl, const float* __restrict__ Bl,
    const float* __restrict__ Wr, const float* __restrict__ Br,
    float* __restrict__ Yr)
{
    const float* W = (blockIdx.y == 0) ? Wl : Wr;
    const float* B = (blockIdx.y == 0) ? Bl : Br;

    __shared__ float2 xs[32 * 128];           // [row_pair][k]
    const int tx = threadIdx.x, ty = threadIdx.y;
    const int t  = ty * 32 + tx;
    const int r0 = blockIdx.x * 64;

    #pragma unroll
    for (int i = 0; i < 4; i++) {
        int u  = t + 256 * i;                 // 0..1023
        int rp = u >> 5, c4 = u & 31;
        int ra = r0 + 2 * rp, rb = ra + 1;
        float4 a = (ra < N_NODES) ? *(const float4*)(X + ra * D + c4 * 4) : make_float4(0,0,0,0);
        float4 b = (rb < N_NODES) ? *(const float4*)(X + rb * D + c4 * 4) : make_float4(0,0,0,0);
        xs[rp * 128 + 4 * c4 + 0] = make_float2(a.x, b.x);
        xs[rp * 128 + 4 * c4 + 1] = make_float2(a.y, b.y);
        xs[rp * 128 + 4 * c4 + 2] = make_float2(a.z, b.z);
        xs[rp * 128 + 4 * c4 + 3] = make_float2(a.w, b.w);
    }
    __syncthreads();

    u64 acc[4][4];
    #pragma unroll
    for (int j = 0; j < 4; j++)
        #pragma unroll
        for (int c = 0; c < 4; c++) acc[j][c] = 0ull;

    const float4* W4 = (const float4*)W;
    #pragma unroll 4
    for (int k = 0; k < D; k += 2) {
        float4 wA = W4[k * 32 + tx];
        float4 wB = W4[(k + 1) * 32 + tx];
        u64 wA0 = pk2(wA.x, wA.x), wA1 = pk2(wA.y, wA.y);
        u64 wA2 = pk2(wA.z, wA.z), wA3 = pk2(wA.w, wA.w);
        u64 wB0 = pk2(wB.x, wB.x), wB1 = pk2(wB.y, wB.y);
        u64 wB2 = pk2(wB.z, wB.z), wB3 = pk2(wB.w, wB.w);
        #pragma unroll
        for (int j = 0; j < 4; j++) {
            float4 xv = *(const float4*)&xs[(ty * 4 + j) * 128 + k];
            u64 x0 = pk2(xv.x, xv.y);   // (row_e, row_o) at k
            u64 x1 = pk2(xv.z, xv.w);   // (row_e, row_o) at k+1
            acc[j][0] = ffma2(x0, wA0, acc[j][0]);
            acc[j][1] = ffma2(x0, wA1, acc[j][1]);
            acc[j][2] = ffma2(x0, wA2, acc[j][2]);
            acc[j][3] = ffma2(x0, wA3, acc[j][3]);
            acc[j][0] = ffma2(x1, wB0, acc[j][0]);
            acc[j][1] = ffma2(x1, wB1, acc[j][1]);
            acc[j][2] = ffma2(x1, wB2, acc[j][2]);
            acc[j][3] = ffma2(x1, wB3, acc[j][3]);
        }
    }

    float4 b4 = *(const float4*)(B + tx * 4);
    #pragma unroll
    for (int j = 0; j < 4; j++) {
        int rp = ty * 4 + j;
        int ra = r0 + 2 * rp, rb = ra + 1;
        float e0,o0,e1,o1,e2,o2,e3,o3;
        upk2(acc[j][0], e0, o0); upk2(acc[j][1], e1, o1);
        upk2(acc[j][2], e2, o2); upk2(acc[j][3], e3, o3);
        e0 += b4.x; e1 += b4.y; e2 += b4.z; e3 += b4.w;
        o0 += b4.x; o1 += b4.y; o2 += b4.z; o3 += b4.w;
        if (blockIdx.y == 0) {
            if (ra < N_NODES) {
                __half2 h01 = __floats2half2_rn(e0, e1);
                __half2 h23 = __floats2half2_rn(e2, e3);
                uint2 pk; pk.x = *(uint32_t*)&h01; pk.y = *(uint32_t*)&h23;
                *(uint2*)(g_xlh + ra * D + tx * 4) = pk;
            }
            if (rb < N_NODES) {
                __half2 h01 = __floats2half2_rn(o0, o1);
                __half2 h23 = __floats2half2_rn(o2, o3);
                uint2 pk; pk.x = *(uint32_t*)&h01; pk.y = *(uint32_t*)&h23;
                *(uint2*)(g_xlh + rb * D + tx * 4) = pk;
            }
        } else {
            if (ra < N_NODES)
                *(float4*)(Yr + ra * D + tx * 4) = make_float4(e0, e1, e2, e3);
            if (rb < N_NODES)
                *(float4*)(Yr + rb * D + tx * 4) = make_float4(o0, o1, o2, o3);
        }
    }
}

// ---------------- attention pieces -----------------------------------------
__device__ __forceinline__ float warp_sum(float l) {
    l += __shfl_xor_sync(0xffffffffu, l, 16);
    l += __shfl_xor_sync(0xffffffffu, l, 8);
    l += __shfl_xor_sync(0xffffffffu, l, 4);
    l += __shfl_xor_sync(0xffffffffu, l, 2);
    l += __shfl_xor_sync(0xffffffffu, l, 1);
    return l;
}

__device__ __forceinline__ float4 h4_to_f4(uint2 p) {
    float2 lo = __half22float2(*(__half2*)&p.x);
    float2 hi = __half22float2(*(__half2*)&p.y);
    return make_float4(lo.x, lo.y, hi.x, hi.y);
}

// ---------------- layer-1 attention: fp16 vocab tables (32KB, L1-hot) ------
// No-max softmax (logits O(0.1)); R11 single-stream 1-deep prefetch form.
__global__ __launch_bounds__(256) void attn1_kernel(
    const int* __restrict__ node_ids, const float* __restrict__ emb,
    const float* __restrict__ We, const float* __restrict__ att,
    const float* __restrict__ bias, const float* __restrict__ gam,
    const float* __restrict__ bet, float* __restrict__ out)
{
    int gw   = (blockIdx.x * blockDim.x + threadIdx.x) >> 5;
    int lane = threadIdx.x & 31;
    if (gw >= N_NODES) return;
    int c = lane * 4;

    int vd = __ldg(node_ids + gw);
    float4 xr4 = h4_to_f4(*(const uint2*)(g_trh + vd * D + c));
    float4 r4  = *(const float4*)(emb + vd * D + c);
    float4 We4 = *(const float4*)(We + c);
    float4 at4 = *(const float4*)(att + c);

    int beg = g_rowptr[gw], end = g_rowptr[gw + 1];
    float s = 0.f;
    float ax = 0.f, ay = 0.f, az = 0.f, aw = 0.f;

    int2  e0 = g_csr[beg];
    float wc = __int_as_float(e0.y);
    uint2 xp = *(const uint2*)(g_tlh + (e0.x >> 17) * D + c);

    for (int i = beg; i < end; i++) {
        int   ni  = (i + 1 < end) ? i + 1 : i;
        int2  ne  = g_csr[ni];
        float nw  = __int_as_float(ne.y);
        uint2 nxp = *(const uint2*)(g_tlh + (ne.x >> 17) * D + c);

        float4 xv = h4_to_f4(xp);
        float t0 = xv.x + xr4.x + wc * We4.x; t0 = fmaxf(t0, 0.2f * t0);
        float t1 = xv.y + xr4.y + wc * We4.y; t1 = fmaxf(t1, 0.2f * t1);
        float t2 = xv.z + xr4.z + wc * We4.z; t2 = fmaxf(t2, 0.2f * t2);
        float t3 = xv.w + xr4.w + wc * We4.w; t3 = fmaxf(t3, 0.2f * t3);
        float l = warp_sum(t0 * at4.x + t1 * at4.y + t2 * at4.z + t3 * at4.w);
        float e = __expf(l);
        s  += e;
        ax += e * xv.x;
        ay += e * xv.y;
        az += e * xv.z;
        aw += e * xv.w;
        xp = nxp; wc = nw;
    }

    float inv = 1.0f / s;
    float4 b4 = *(const float4*)(bias + c);
    float hx = r4.x + ax * inv + b4.x;
    float hy = r4.y + ay * inv + b4.y;
    float hz = r4.z + az * inv + b4.z;
    float hw = r4.w + aw * inv + b4.w;

    float mu = warp_sum(hx + hy + hz + hw) * (1.0f / D);
    float dx = hx - mu, dy = hy - mu, dz = hz - mu, dw = hw - mu;
    float var = warp_sum(dx * dx + dy * dy + dz * dz + dw * dw) * (1.0f / D);
    float sc  = rsqrtf(var + 1e-5f);

    float4 g4  = *(const float4*)(gam + c);
    float4 be4 = *(const float4*)(bet + c);
    float4 o;
    o.x = dx * sc * g4.x + be4.x;
    o.y = dy * sc * g4.y + be4.y;
    o.z = dz * sc * g4.z + be4.z;
    o.w = dw * sc * g4.w + be4.w;
    *(float4*)(out + gw * D + c) = o;
}

// ---------------- layer-2 attention: fp16 xl gather, no-max softmax --------
// R11 single-stream 1-deep prefetch form (depth-2 pipeline regressed in R12).
__global__ __launch_bounds__(256) void attn2_kernel(
    const float* __restrict__ xr,
    const float* __restrict__ We, const float* __restrict__ att,
    const float* __restrict__ bias, const float* __restrict__ gam,
    const float* __restrict__ bet, const float* __restrict__ resid,
    float* __restrict__ out)
{
    int gw   = (blockIdx.x * blockDim.x + threadIdx.x) >> 5;
    int lane = threadIdx.x & 31;
    if (gw >= N_NODES) return;
    int c = lane * 4;

    float4 xr4 = *(const float4*)(xr + gw * D + c);
    float4 We4 = *(const float4*)(We + c);
    float4 at4 = *(const float4*)(att + c);

    int beg = g_rowptr[gw], end = g_rowptr[gw + 1];
    float s = 0.f;
    float ax = 0.f, ay = 0.f, az = 0.f, aw = 0.f;

    int2  e0 = g_csr[beg];
    float wc = __int_as_float(e0.y);
    uint2 xp = *(const uint2*)(g_xlh + (e0.x & 0x1FFFF) * D + c);

    for (int i = beg; i < end; i++) {
        int   ni  = (i + 1 < end) ? i + 1 : i;
        int2  ne  = g_csr[ni];
        float nw  = __int_as_float(ne.y);
        uint2 nxp = *(const uint2*)(g_xlh + (ne.x & 0x1FFFF) * D + c);

        float4 xv = h4_to_f4(xp);
        float t0 = xv.x + xr4.x + wc * We4.x; t0 = fmaxf(t0, 0.2f * t0);
        float t1 = xv.y + xr4.y + wc * We4.y; t1 = fmaxf(t1, 0.2f * t1);
        float t2 = xv.z + xr4.z + wc * We4.z; t2 = fmaxf(t2, 0.2f * t2);
        float t3 = xv.w + xr4.w + wc * We4.w; t3 = fmaxf(t3, 0.2f * t3);
        float l = warp_sum(t0 * at4.x + t1 * at4.y + t2 * at4.z + t3 * at4.w);
        float e = __expf(l);
        s  += e;
        ax += e * xv.x;
        ay += e * xv.y;
        az += e * xv.z;
        aw += e * xv.w;
        xp = nxp; wc = nw;
    }

    float inv = 1.0f / s;
    float4 b4 = *(const float4*)(bias + c);
    float4 r4 = *(const float4*)(resid + gw * D + c);
    float hx = r4.x + ax * inv + b4.x;
    float hy = r4.y + ay * inv + b4.y;
    float hz = r4.z + az * inv + b4.z;
    float hw = r4.w + aw * inv + b4.w;

    float mu = warp_sum(hx + hy + hz + hw) * (1.0f / D);
    float dx = hx - mu, dy = hy - mu, dz = hz - mu, dw = hw - mu;
    float var = warp_sum(dx * dx + dy * dy + dz * dz + dw * dw) * (1.0f / D);
    float sc  = rsqrtf(var + 1e-5f);

    float4 g4  = *(const float4*)(gam + c);
    float4 be4 = *(const float4*)(bet + c);
    float4 o;
    o.x = dx * sc * g4.x + be4.x;
    o.y = dy * sc * g4.y + be4.y;
    o.z = dz * sc * g4.z + be4.z;
    o.w = dw * sc * g4.w + be4.w;
    *(float4*)(out + gw * D + c) = o;
}

// ---------------- host -----------------------------------------------------
extern "C" void kernel_launch(void* const* d_in, const int* in_sizes, int n_in,
                              void* d_out, int out_size)
{
    const int*   node_ids = (const int*)d_in[0];
    const int*   ei       = (const int*)d_in[1];
    const float* ew       = (const float*)d_in[2];
    const float* emb      = (const float*)d_in[3];
    const float* w1l = (const float*)d_in[4];
    const float* b1l = (const float*)d_in[5];
    const float* w1r = (const float*)d_in[6];
    const float* b1r = (const float*)d_in[7];
    const float* w1e = (const float*)d_in[8];
    const float* at1 = (const float*)d_in[9];
    const float* bi1 = (const float*)d_in[10];
    const float* g1  = (const float*)d_in[11];
    const float* be1 = (const float*)d_in[12];
    const float* w2l = (const float*)d_in[13];
    const float* b2l = (const float*)d_in[14];
    const float* w2r = (const float*)d_in[15];
    const float* b2r = (const float*)d_in[16];
    const float* w2e = (const float*)d_in[17];
    const float* at2 = (const float*)d_in[18];
    const float* bi2 = (const float*)d_in[19];
    const float* g2  = (const float*)d_in[20];
    const float* be2 = (const float*)d_in[21];
    float* out = (float*)d_out;

    float *xr, *x1;
    cudaGetSymbolAddress((void**)&xr, g_xr);
    cudaGetSymbolAddress((void**)&x1, g_x1);

    dim3 gb(32, 8);
    dim3 gemm_grid((N_NODES + 63) / 64, 2);      // 782 x 2
    dim3 tbl_grid(16, 2);
    const int AB = (N_NODES + 7) / 8;            // 6250 (8 warps/block)

    setup_kernel<<<(N_NODES + 256) / 256, 256>>>();                           // 1
    hist_sumw_kernel<<<(N_EDGES + 255) / 256, 256>>>(ei, ew);                 // 2
    table_kernel<<<tbl_grid, 256>>>(emb, w1l, b1l, w1r, b1r);                 // 3
    scan_pb_kernel<<<SCAN_NBLK, 256>>>();                                     // 4 <- profiled
    scan_final_kernel<<<SCAN_NBLK, 256>>>();                                  // 5
    scatter_kernel<<<(M_TOT + 255) / 256, 256>>>(ei, ew, node_ids);           // 6
    attn1_kernel<<<AB, 256>>>(node_ids, emb, w1e, at1, bi1, g1, be1, x1);     // 7
    gemm2_kernel<<<gemm_grid, gb>>>(x1, w2l, b2l, w2r, b2r, xr);              // 8
    attn2_kernel<<<AB, 256>>>(xr, w2e, at2, bi2, g2, be2, x1, out);           // 9
}